// round 10
// baseline (speedup 1.0000x reference)
#include <cuda_runtime.h>
#include <cuda_fp16.h>
#include <mma.h>
#include <math.h>

using namespace nvcuda;

// ---------------- problem constants ----------------
#define NN 10000
#define EE 320000
#define HH 128
#define GG 50
#define LL 6
#define KTAB 4096
#define PTS 16

#define AP 136       // padded smem row stride (halves)
#define OP 132       // padded smem row stride (floats)
#define ASZ (64 * AP * 2)     // 17408
#define BSZ (128 * AP * 2)    // 34816
#define SMEM_CHAIN (ASZ + 2 * BSZ)  // 87040

#define DMAXT 8.6605f
#define TABSCALE ((float)(KTAB - 1) / DMAXT)
#define DSTEP (DMAXT / (float)(KTAB - 1))
#define GSTEP (10.0f / 49.0f)
#define GCOEFF (-0.5f / (GSTEP * GSTEP))
#define LN2F 0.6931471805599453f
#define PIF 3.14159265358979323846f

// ---------------- scratch ----------------
__device__ __half g_tab[LL * KTAB * HH];
__device__ __half g_xh[NN * HH];
__device__ __half g_aggh[NN * HH];
__device__ __half g_hh[NN * HH];
__device__ __half g_w1t[LL * HH * HH];
__device__ __half g_w2t[LL * HH * HH];
__device__ __half g_w3t[LL * HH * HH];
__device__ int    g_deg[NN];
__device__ int    g_start[NN + 1];
__device__ int    g_cursor[NN];
__device__ int2   g_me[EE];
__device__ int2   g_se[EE];

__device__ __forceinline__ float sspf(float v) {
    float sp = (v > 20.f) ? v : log1pf(expf(v));
    return sp - LN2F;
}

__device__ __forceinline__ void cp16(void* dst, const void* src) {
    unsigned s = (unsigned)__cvta_generic_to_shared(dst);
    asm volatile("cp.async.cg.shared.global [%0], [%1], 16;"
                 :: "r"(s), "l"(src));
}
__device__ __forceinline__ void cp16z(void* dst, const void* src, int valid) {
    unsigned s = (unsigned)__cvta_generic_to_shared(dst);
    int sz = valid ? 16 : 0;
    asm volatile("cp.async.cg.shared.global [%0], [%1], 16, %2;"
                 :: "r"(s), "l"(src), "r"(sz));
}
#define CP_COMMIT() asm volatile("cp.async.commit_group;" ::: "memory")
#define CP_WAIT_ALL() asm volatile("cp.async.wait_group 0;" ::: "memory")

// ---------------- weight transpose + fp16 convert ----------------
__global__ void k_wconv(const float* __restrict__ w1,
                        const float* __restrict__ w2,
                        const float* __restrict__ w3)
{
    const int SET = LL * HH * HH;
    int idx = blockIdx.x * blockDim.x + threadIdx.x;
    if (idx >= 3 * SET) return;
    int which = idx / SET;
    int r = idx - which * SET;
    int l = r >> 14;
    int k = (r >> 7) & 127;
    int n = r & 127;
    const float* in = (which == 0) ? w1 : (which == 1) ? w2 : w3;
    __half* out = (which == 0) ? g_w1t : (which == 1) ? g_w2t : g_w3t;
    out[l * HH * HH + n * HH + k] = __float2half(in[r]);
}

// ---------------- embedding ----------------
__global__ void k_embed(const int* __restrict__ z, const float* __restrict__ emb,
                        float* __restrict__ h, int N) {
    int idx = blockIdx.x * blockDim.x + threadIdx.x;
    if (idx >= N * 32) return;
    int n = idx >> 5, q = idx & 31;
    float4 v = ((const float4*)emb)[z[n] * 32 + q];
    ((float4*)h)[idx] = v;
    uint2 p;
    __half2 h0 = __floats2half2_rn(v.x, v.y);
    __half2 h1 = __floats2half2_rn(v.z, v.w);
    p.x = *(unsigned int*)&h0;
    p.y = *(unsigned int*)&h1;
    ((uint2*)g_hh)[idx] = p;
}

__global__ void k_zero(int n) {
    int i = blockIdx.x * blockDim.x + threadIdx.x;
    if (i < n) g_deg[i] = 0;
}

// ---------------- initial lin1 (padded smem) ----------------
__global__ void __launch_bounds__(256) k_lin1(int N) {
    __shared__ __align__(16) char smem_raw[64 * AP * 2 + 128 * AP * 2];
    __half* As = (__half*)smem_raw;
    __half* Bs = (__half*)(smem_raw + 64 * AP * 2);
    float*  Os = (float*)smem_raw;

    const int tid = threadIdx.x;
    const int wid = tid >> 5;
    const int m0 = blockIdx.x * 64;
    const __half* Bw = g_w1t;  // layer 0

#pragma unroll
    for (int i = 0; i < 4; i++) {
        int lin = i * 256 + tid;
        int r = lin >> 4, c = lin & 15;
        int gr = m0 + r;
        uint4 v = make_uint4(0, 0, 0, 0);
        if (gr < N) v = *(const uint4*)(g_hh + (size_t)gr * HH + c * 8);
        *(uint4*)(As + r * AP + c * 8) = v;
    }
#pragma unroll
    for (int i = 0; i < 8; i++) {
        int lin = i * 256 + tid;
        int r = lin >> 4, c = lin & 15;
        *(uint4*)(Bs + r * AP + c * 8) = *(const uint4*)(Bw + lin * 8);
    }
    __syncthreads();

    const int wm = wid & 3;
    const int wn = wid >> 2;
    wmma::fragment<wmma::accumulator, 16, 16, 16, float> accf[4];
#pragma unroll
    for (int n = 0; n < 4; n++) wmma::fill_fragment(accf[n], 0.f);
#pragma unroll
    for (int ks = 0; ks < 8; ks++) {
        wmma::fragment<wmma::matrix_a, 16, 16, 16, __half, wmma::row_major> af;
        wmma::load_matrix_sync(af, As + (wm * 16) * AP + ks * 16, AP);
#pragma unroll
        for (int n = 0; n < 4; n++) {
            wmma::fragment<wmma::matrix_b, 16, 16, 16, __half, wmma::col_major> bf;
            wmma::load_matrix_sync(bf, Bs + (wn * 64 + n * 16) * AP + ks * 16, AP);
            wmma::mma_sync(accf[n], af, bf, accf[n]);
        }
    }
    __syncthreads();
#pragma unroll
    for (int n = 0; n < 4; n++)
        wmma::store_matrix_sync(Os + (wm * 16) * OP + wn * 64 + n * 16,
                                accf[n], OP, wmma::mem_row_major);
    __syncthreads();

#pragma unroll
    for (int i = 0; i < 8; i++) {
        int lin = i * 256 + tid;
        int r = lin >> 5, c4 = lin & 31;
        int gr = m0 + r;
        if (gr >= N) continue;
        float4 v = *(float4*)(Os + r * OP + c4 * 4);
        uint2 p;
        __half2 h0 = __floats2half2_rn(v.x, v.y);
        __half2 h1 = __floats2half2_rn(v.z, v.w);
        p.x = *(unsigned int*)&h0;
        p.y = *(unsigned int*)&h1;
        *(uint2*)(g_xh + (size_t)gr * HH + c4 * 4) = p;
    }
}

// ---------------- Wf(d) table build ----------------
__global__ void __launch_bounds__(128) k_table(
    const float* __restrict__ w1, const float* __restrict__ b1,
    const float* __restrict__ w2, const float* __restrict__ b2)
{
    __shared__ float ea[PTS][GG];
    __shared__ float t1[PTS][HH];
    const int l  = blockIdx.y;
    const int k0 = blockIdx.x * PTS;
    const int f  = threadIdx.x;

    for (int idx = f; idx < PTS * GG; idx += 128) {
        int p = idx / GG, g = idx % GG;
        float d  = (float)(k0 + p) * DSTEP;
        float dd = d - (float)g * GSTEP;
        ea[p][g] = expf(GCOEFF * dd * dd);
    }
    __syncthreads();

    float acc[PTS];
#pragma unroll
    for (int p = 0; p < PTS; p++) acc[p] = 0.f;
    const float* W1 = w1 + l * GG * HH;
    for (int g = 0; g < GG; g++) {
        float w = W1[g * HH + f];
#pragma unroll
        for (int p = 0; p < PTS; p++) acc[p] += ea[p][g] * w;
    }
    float bb = b1[l * HH + f];
#pragma unroll
    for (int p = 0; p < PTS; p++) t1[p][f] = sspf(acc[p] + bb);
    __syncthreads();

#pragma unroll
    for (int p = 0; p < PTS; p++) acc[p] = 0.f;
    const float* W2 = w2 + l * HH * HH;
    for (int ff = 0; ff < HH; ff++) {
        float w = W2[ff * HH + f];
#pragma unroll
        for (int p = 0; p < PTS; p++) acc[p] += t1[p][ff] * w;
    }
    float b2v = b2[l * HH + f];
#pragma unroll
    for (int p = 0; p < PTS; p++) {
        float d = (float)(k0 + p) * DSTEP;
        float C = 0.5f * (cosf(d * (PIF / 10.f)) + 1.f);
        g_tab[(size_t)(l * KTAB + k0 + p) * HH + f] =
            __float2half((acc[p] + b2v) * C);
    }
}

// ---------------- CSR build ----------------
__global__ void k_prep(const int* __restrict__ ei, const float* __restrict__ pos, int E) {
    int stride = gridDim.x * blockDim.x;
    for (int e = blockIdx.x * blockDim.x + threadIdx.x; e < E; e += stride) {
        int r = ei[e], c = ei[E + e];
        float dx = pos[r * 3 + 0] - pos[c * 3 + 0];
        float dy = pos[r * 3 + 1] - pos[c * 3 + 1];
        float dz = pos[r * 3 + 2] - pos[c * 3 + 2];
        float d = sqrtf(dx * dx + dy * dy + dz * dz);
        float u = d * TABSCALE;
        int k = (int)u;
        if (k > KTAB - 2) k = KTAB - 2;
        if (k < 0) k = 0;
        float t = u - (float)k;
        g_me[e] = make_int2(r | (k << 14), __float_as_int(t));
        atomicAdd(&g_deg[c], 1);
    }
}

__global__ void __launch_bounds__(1024) k_scan(int n) {
    __shared__ int sw[32];
    const int PER = 10;
    int t = threadIdx.x, lane = t & 31, w = t >> 5;
    int base = t * PER;
    int local[PER];
    int sum = 0;
#pragma unroll
    for (int i = 0; i < PER; i++) {
        int v = (base + i < n) ? g_deg[base + i] : 0;
        local[i] = sum;
        sum += v;
    }
    int inc = sum;
#pragma unroll
    for (int off = 1; off < 32; off <<= 1) {
        int v = __shfl_up_sync(0xffffffffu, inc, off);
        if (lane >= off) inc += v;
    }
    if (lane == 31) sw[w] = inc;
    __syncthreads();
    if (w == 0) {
        int v = sw[lane];
        int s2 = v;
#pragma unroll
        for (int off = 1; off < 32; off <<= 1) {
            int u2 = __shfl_up_sync(0xffffffffu, s2, off);
            if (lane >= off) s2 += u2;
        }
        sw[lane] = s2 - v;
        if (lane == 31) g_start[n] = s2;
    }
    __syncthreads();
    int excl = sw[w] + inc - sum;
#pragma unroll
    for (int i = 0; i < PER; i++) {
        if (base + i < n) {
            int st = excl + local[i];
            g_start[base + i]  = st;
            g_cursor[base + i] = st;
        }
    }
}

__global__ void k_scatter(const int* __restrict__ ei, int E) {
    int stride = gridDim.x * blockDim.x;
    for (int e = blockIdx.x * blockDim.x + threadIdx.x; e < E; e += stride) {
        int c = ei[E + e];
        int p = atomicAdd(&g_cursor[c], 1);
        g_se[p] = g_me[e];
    }
}

// ---------------- message aggregation (fp16 lerp, MLP x2, PDL) ----
__global__ void __launch_bounds__(256) k_agg(int l, int N) {
    cudaGridDependencySynchronize();  // PDL: wait for prior chain's g_xh
    int warp = (blockIdx.x * 256 + threadIdx.x) >> 5;
    int lane = threadIdx.x & 31;
    if (warp >= N) return;
    const __half* __restrict__ tab = g_tab + (size_t)l * KTAB * HH;
    int beg = g_start[warp], end = g_start[warp + 1];
    const int flane = lane & 15;
    const int esub  = lane >> 4;
    float acc[8];
#pragma unroll
    for (int q = 0; q < 8; q++) acc[q] = 0.f;

    for (int e0 = beg; e0 < end; e0 += 32) {
        int idx = e0 + lane;
        int2 mv = make_int2(0, 0);
        if (idx < end) mv = g_se[idx];
        int cnt = min(32, end - e0);
        for (int s = 0; s < cnt; s += 4) {
            int j1 = s + esub;
            int j2 = s + 2 + esub;
            int mj1 = __shfl_sync(0xffffffffu, mv.x, j1 & 31);
            int ti1 = __shfl_sync(0xffffffffu, mv.y, j1 & 31);
            int mj2 = __shfl_sync(0xffffffffu, mv.x, j2 & 31);
            int ti2 = __shfl_sync(0xffffffffu, mv.y, j2 & 31);
            bool p1 = j1 < cnt, p2 = j2 < cnt;
            uint4 xr1, w01, w11, xr2, w02, w12;
            int k1 = mj1 >> 14, k2 = mj2 >> 14;
            int s1 = mj1 & 0x3FFF, s2v = mj2 & 0x3FFF;
            if (p1) {
                xr1 = *(const uint4*)(g_xh + (size_t)s1 * HH + flane * 8);
                w01 = *(const uint4*)(tab + (size_t)k1 * HH + flane * 8);
                w11 = *(const uint4*)(tab + (size_t)(k1 + 1) * HH + flane * 8);
            }
            if (p2) {
                xr2 = *(const uint4*)(g_xh + (size_t)s2v * HH + flane * 8);
                w02 = *(const uint4*)(tab + (size_t)k2 * HH + flane * 8);
                w12 = *(const uint4*)(tab + (size_t)(k2 + 1) * HH + flane * 8);
            }
            if (p1) {
                __half2 t2 = __float2half2_rn(__int_as_float(ti1));
                const __half2* xv = (const __half2*)&xr1;
                const __half2* a0 = (const __half2*)&w01;
                const __half2* a1 = (const __half2*)&w11;
#pragma unroll
                for (int q = 0; q < 4; q++) {
                    __half2 dd = __hsub2(a1[q], a0[q]);
                    __half2 w  = __hfma2(t2, dd, a0[q]);
                    __half2 p  = __hmul2(w, xv[q]);
                    float2 pf = __half22float2(p);
                    acc[q * 2 + 0] += pf.x;
                    acc[q * 2 + 1] += pf.y;
                }
            }
            if (p2) {
                __half2 t2 = __float2half2_rn(__int_as_float(ti2));
                const __half2* xv = (const __half2*)&xr2;
                const __half2* a0 = (const __half2*)&w02;
                const __half2* a1 = (const __half2*)&w12;
#pragma unroll
                for (int q = 0; q < 4; q++) {
                    __half2 dd = __hsub2(a1[q], a0[q]);
                    __half2 w  = __hfma2(t2, dd, a0[q]);
                    __half2 p  = __hmul2(w, xv[q]);
                    float2 pf = __half22float2(p);
                    acc[q * 2 + 0] += pf.x;
                    acc[q * 2 + 1] += pf.y;
                }
            }
        }
    }
#pragma unroll
    for (int q = 0; q < 8; q++)
        acc[q] += __shfl_xor_sync(0xffffffffu, acc[q], 16);

    if (esub == 0) {
        uint4 outv;
        __half2* op = (__half2*)&outv;
#pragma unroll
        for (int q = 0; q < 4; q++)
            op[q] = __floats2half2_rn(acc[q * 2], acc[q * 2 + 1]);
        *(uint4*)(g_aggh + (size_t)warp * HH + flane * 8) = outv;
    }
    cudaTriggerProgrammaticLaunchCompletion();
}

// ---------------- fused GEMM chain: cp.async ping-pong + PDL ----------------
// smem: As | B0 | B1.  W2->B0, W3->B1 prefetched BEFORE the PDL grid sync.
// Os overlays the B-buffer just consumed (all accums in regs before store).
template <bool NEXT>
__global__ void __launch_bounds__(256, 2) k_chain(
    int l, const float* __restrict__ b2p, const float* __restrict__ b3p,
    float* __restrict__ h, int N)
{
    extern __shared__ __align__(16) char sm[];
    __half* As = (__half*)sm;
    __half* B0 = (__half*)(sm + ASZ);
    __half* B1 = (__half*)(sm + ASZ + BSZ);

    const int tid = threadIdx.x;
    const int wid = tid >> 5;
    const int m0  = blockIdx.x * 64;

    // prefetch W2 -> B0, W3 -> B1 (independent of agg output)
    {
        const __half* W2 = g_w2t + (size_t)l * HH * HH;
        const __half* W3 = g_w3t + (size_t)l * HH * HH;
#pragma unroll
        for (int i = 0; i < 8; i++) {
            int lin = i * 256 + tid;
            int r = lin >> 4, c = lin & 15;
            cp16(B0 + r * AP + c * 8, W2 + lin * 8);
        }
#pragma unroll
        for (int i = 0; i < 8; i++) {
            int lin = i * 256 + tid;
            int r = lin >> 4, c = lin & 15;
            cp16(B1 + r * AP + c * 8, W3 + lin * 8);
        }
        CP_COMMIT();
    }

    cudaGridDependencySynchronize();  // PDL: agg output now visible

    // As <- g_aggh (cp.async, zero-fill OOB rows)
#pragma unroll
    for (int i = 0; i < 4; i++) {
        int lin = i * 256 + tid;
        int r = lin >> 4, c = lin & 15;
        int gr = m0 + r;
        int valid = gr < N;
        const void* src = g_aggh + (size_t)(valid ? gr : 0) * HH + c * 8;
        cp16z(As + r * AP + c * 8, src, valid);
    }
    CP_COMMIT();
    CP_WAIT_ALL();
    __syncthreads();

    // one GEMM stage: accumulate 64x128 = (As @ Bs^T) fully in regs,
    // sync, then store to Os (which may overlay Bs).
    auto wmma_stage = [&](const __half* Bs, float* Os) {
        wmma::fragment<wmma::accumulator, 16, 16, 16, float> acc[2][2];
#pragma unroll
        for (int it = 0; it < 2; it++) {
            int t2 = wid + it * 8;
            int wm = t2 & 3, wn = t2 >> 2;
            wmma::fill_fragment(acc[it][0], 0.f);
            wmma::fill_fragment(acc[it][1], 0.f);
#pragma unroll
            for (int ks = 0; ks < 8; ks++) {
                wmma::fragment<wmma::matrix_a, 16, 16, 16, __half, wmma::row_major> af;
                wmma::load_matrix_sync(af, As + (wm * 16) * AP + ks * 16, AP);
                wmma::fragment<wmma::matrix_b, 16, 16, 16, __half, wmma::col_major> bf0, bf1;
                wmma::load_matrix_sync(bf0, Bs + (wn * 32) * AP + ks * 16, AP);
                wmma::load_matrix_sync(bf1, Bs + (wn * 32 + 16) * AP + ks * 16, AP);
                wmma::mma_sync(acc[it][0], af, bf0, acc[it][0]);
                wmma::mma_sync(acc[it][1], af, bf1, acc[it][1]);
            }
        }
        __syncthreads();  // all As/Bs reads done -> safe to overlay Os
#pragma unroll
        for (int it = 0; it < 2; it++) {
            int t2 = wid + it * 8;
            int wm = t2 & 3, wn = t2 >> 2;
            wmma::store_matrix_sync(Os + (wm * 16) * OP + wn * 32,
                                    acc[it][0], OP, wmma::mem_row_major);
            wmma::store_matrix_sync(Os + (wm * 16) * OP + wn * 32 + 16,
                                    acc[it][1], OP, wmma::mem_row_major);
        }
        __syncthreads();
    };

    // ---- Stage 1: u = ssp(agg @ W2 + b2) -> As  (Os over B0) ----
    {
        float* Os = (float*)(sm + ASZ);
        wmma_stage(B0, Os);
#pragma unroll
        for (int i = 0; i < 8; i++) {
            int lin = i * 256 + tid;
            int r = lin >> 5, c4 = lin & 31;
            float4 v = *(float4*)(Os + r * OP + c4 * 4);
            const float4 bi = *(const float4*)(b2p + c4 * 4);
            v.x = sspf(v.x + bi.x); v.y = sspf(v.y + bi.y);
            v.z = sspf(v.z + bi.z); v.w = sspf(v.w + bi.w);
            uint2 p;
            __half2 h0 = __floats2half2_rn(v.x, v.y);
            __half2 h1 = __floats2half2_rn(v.z, v.w);
            p.x = *(unsigned int*)&h0;
            p.y = *(unsigned int*)&h1;
            *(uint2*)(As + (size_t)r * AP + c4 * 4) = p;
        }
        __syncthreads();  // Os fully consumed, As written
    }

    // prefetch W1[l+1] -> B0 region (over dead Os), overlaps stage 2
    if (NEXT) {
        const __half* W1 = g_w1t + (size_t)(l + 1) * HH * HH;
#pragma unroll
        for (int i = 0; i < 8; i++) {
            int lin = i * 256 + tid;
            int r = lin >> 4, c = lin & 15;
            cp16(B0 + r * AP + c * 8, W1 + lin * 8);
        }
        CP_COMMIT();
    }

    // ---- Stage 2: v = u @ W3 + b3 + h ; h = v -> As  (Os over B1) ----
    {
        float* Os = (float*)(sm + ASZ + BSZ);
        wmma_stage(B1, Os);
#pragma unroll
        for (int i = 0; i < 8; i++) {
            int lin = i * 256 + tid;
            int r = lin >> 5, c4 = lin & 31;
            int gr = m0 + r;
            float4 v = *(float4*)(Os + r * OP + c4 * 4);
            const float4 bi = *(const float4*)(b3p + c4 * 4);
            v.x += bi.x; v.y += bi.y; v.z += bi.z; v.w += bi.w;
            if (gr < N) {
                float4 o = *(float4*)(h + (size_t)gr * HH + c4 * 4);
                v.x += o.x; v.y += o.y; v.z += o.z; v.w += o.w;
                *(float4*)(h + (size_t)gr * HH + c4 * 4) = v;
            }
            uint2 p;
            __half2 h0 = __floats2half2_rn(v.x, v.y);
            __half2 h1 = __floats2half2_rn(v.z, v.w);
            p.x = *(unsigned int*)&h0;
            p.y = *(unsigned int*)&h1;
            *(uint2*)(As + (size_t)r * AP + c4 * 4) = p;
        }
        __syncthreads();
    }

    // ---- Stage 3: x_{l+1} = v @ W1[l+1] -> g_xh  (Os over B1) ----
    if (NEXT) {
        CP_WAIT_ALL();
        __syncthreads();  // W1 resident in B0
        float* Os = (float*)(sm + ASZ + BSZ);
        wmma_stage(B0, Os);
#pragma unroll
        for (int i = 0; i < 8; i++) {
            int lin = i * 256 + tid;
            int r = lin >> 5, c4 = lin & 31;
            int gr = m0 + r;
            if (gr >= N) continue;
            float4 v = *(float4*)(Os + r * OP + c4 * 4);
            uint2 p;
            __half2 h0 = __floats2half2_rn(v.x, v.y);
            __half2 h1 = __floats2half2_rn(v.z, v.w);
            p.x = *(unsigned int*)&h0;
            p.y = *(unsigned int*)&h1;
            *(uint2*)(g_xh + (size_t)gr * HH + c4 * 4) = p;
        }
    }
    cudaTriggerProgrammaticLaunchCompletion();
}

// ---------------- PDL launch helper ----------------
template <typename K, typename... Args>
static void launch_pdl(K kern, dim3 grid, dim3 block, size_t smem,
                       cudaStream_t st, Args... args)
{
    cudaLaunchConfig_t cfg = {};
    cfg.gridDim = grid;
    cfg.blockDim = block;
    cfg.dynamicSmemBytes = smem;
    cfg.stream = st;
    cudaLaunchAttribute at[1];
    at[0].id = cudaLaunchAttributeProgrammaticStreamSerialization;
    at[0].val.programmaticStreamSerializationAllowed = 1;
    cfg.attrs = at;
    cfg.numAttrs = 1;
    cudaLaunchKernelEx(&cfg, kern, args...);
}

// ---------------- launch ----------------
extern "C" void kernel_launch(void* const* d_in, const int* in_sizes, int n_in,
                              void* d_out, int out_size)
{
    const int*   z      = (const int*)d_in[0];
    const float* pos    = (const float*)d_in[1];
    const int*   ei     = (const int*)d_in[2];
    const float* emb    = (const float*)d_in[3];
    const float* mlp_w1 = (const float*)d_in[4];
    const float* mlp_b1 = (const float*)d_in[5];
    const float* mlp_w2 = (const float*)d_in[6];
    const float* mlp_b2 = (const float*)d_in[7];
    const float* lin1_w = (const float*)d_in[8];
    const float* lin2_w = (const float*)d_in[9];
    const float* lin2_b = (const float*)d_in[10];
    const float* lin_w  = (const float*)d_in[11];
    const float* lin_b  = (const float*)d_in[12];

    const int N = in_sizes[0];
    const int E = in_sizes[2] / 2;
    float* h = (float*)d_out;

    static bool s_init = false;
    static cudaStream_t s_csr, s_tab;
    static cudaEvent_t s_evRoot, s_evCsr, s_evTab;
    if (!s_init) {
        cudaFuncSetAttribute(k_chain<true>,
                             cudaFuncAttributeMaxDynamicSharedMemorySize, SMEM_CHAIN);
        cudaFuncSetAttribute(k_chain<false>,
                             cudaFuncAttributeMaxDynamicSharedMemorySize, SMEM_CHAIN);
        cudaStreamCreateWithFlags(&s_csr, cudaStreamNonBlocking);
        cudaStreamCreateWithFlags(&s_tab, cudaStreamNonBlocking);
        cudaEventCreateWithFlags(&s_evRoot, cudaEventDisableTiming);
        cudaEventCreateWithFlags(&s_evCsr, cudaEventDisableTiming);
        cudaEventCreateWithFlags(&s_evTab, cudaEventDisableTiming);
        s_init = true;
    }

    const int gb = (N + 63) / 64;
    const int ga = (N + 7) / 8;

    cudaEventRecord(s_evRoot, 0);
    cudaStreamWaitEvent(s_csr, s_evRoot, 0);
    cudaStreamWaitEvent(s_tab, s_evRoot, 0);

    // CSR stream
    k_zero<<<(N + 255) / 256, 256, 0, s_csr>>>(N);
    k_prep<<<313, 256, 0, s_csr>>>(ei, pos, E);
    k_scan<<<1, 1024, 0, s_csr>>>(N);
    k_scatter<<<313, 256, 0, s_csr>>>(ei, E);
    cudaEventRecord(s_evCsr, s_csr);

    // table stream
    dim3 tg(KTAB / PTS, LL);
    k_table<<<tg, 128, 0, s_tab>>>(mlp_w1, mlp_b1, mlp_w2, mlp_b2);
    cudaEventRecord(s_evTab, s_tab);

    // main stream
    k_wconv<<<(3 * LL * HH * HH + 255) / 256, 256>>>(lin1_w, lin2_w, lin_w);
    k_embed<<<(N * 32 + 255) / 256, 256>>>(z, emb, h, N);
    k_lin1<<<gb, 256>>>(N);

    cudaStreamWaitEvent(0, s_evCsr, 0);
    cudaStreamWaitEvent(0, s_evTab, 0);

    for (int l = 0; l < LL; l++) {
        launch_pdl(k_agg, dim3(ga), dim3(256), 0, (cudaStream_t)0, l, N);
        if (l < LL - 1)
            launch_pdl(k_chain<true>, dim3(gb), dim3(256), (size_t)SMEM_CHAIN,
                       (cudaStream_t)0, l, lin2_b + (size_t)l * HH,
                       lin_b + (size_t)l * HH, h, N);
        else
            launch_pdl(k_chain<false>, dim3(gb), dim3(256), (size_t)SMEM_CHAIN,
                       (cudaStream_t)0, l, lin2_b + (size_t)l * HH,
                       lin_b + (size_t)l * HH, h, N);
    }
}

// round 11
// speedup vs baseline: 1.0230x; 1.0230x over previous
#include <cuda_runtime.h>
#include <cuda_fp16.h>
#include <mma.h>
#include <math.h>

using namespace nvcuda;

// ---------------- problem constants ----------------
#define NN 10000
#define EE 320000
#define HH 128       // hidden = filters = 128
#define GG 50        // gaussians
#define LL 6         // layers
#define KTAB 2048    // distance-table resolution (512KB/layer -> L1-cacheable)
#define PTS 16       // grid points per table-build block

#define AP 136       // padded smem row stride (halves) -> conflict-free
#define OP 132       // padded smem row stride (floats)

#define DMAXT 8.6605f
#define TABSCALE ((float)(KTAB - 1) / DMAXT)
#define DSTEP (DMAXT / (float)(KTAB - 1))
#define GSTEP (10.0f / 49.0f)
#define GCOEFF (-0.5f / (GSTEP * GSTEP))
#define LN2F 0.6931471805599453f
#define PIF 3.14159265358979323846f

// ---------------- scratch ----------------
__device__ __half g_tab[LL * KTAB * HH];
__device__ __half g_xh[NN * HH];
__device__ __half g_aggh[NN * HH];
__device__ __half g_hh[NN * HH];
__device__ __half g_w1t[LL * HH * HH];
__device__ __half g_w2t[LL * HH * HH];
__device__ __half g_w3t[LL * HH * HH];
__device__ int    g_deg[NN];
__device__ int    g_start[NN + 1];
__device__ int    g_cursor[NN];
__device__ int2   g_me[EE];
__device__ int2   g_se[EE];

__device__ __forceinline__ float sspf(float v) {
    float sp = (v > 20.f) ? v : log1pf(expf(v));
    return sp - LN2F;
}

// ---------------- weight transpose + fp16 convert ----------------
__global__ void k_wconv(const float* __restrict__ w1,
                        const float* __restrict__ w2,
                        const float* __restrict__ w3)
{
    const int SET = LL * HH * HH;
    int idx = blockIdx.x * blockDim.x + threadIdx.x;
    if (idx >= 3 * SET) return;
    int which = idx / SET;
    int r = idx - which * SET;
    int l = r >> 14;
    int k = (r >> 7) & 127;
    int n = r & 127;
    const float* in = (which == 0) ? w1 : (which == 1) ? w2 : w3;
    __half* out = (which == 0) ? g_w1t : (which == 1) ? g_w2t : g_w3t;
    out[l * HH * HH + n * HH + k] = __float2half(in[r]);
}

// ---------------- embedding ----------------
__global__ void k_embed(const int* __restrict__ z, const float* __restrict__ emb,
                        float* __restrict__ h, int N) {
    int idx = blockIdx.x * blockDim.x + threadIdx.x;
    if (idx >= N * 32) return;
    int n = idx >> 5, q = idx & 31;
    float4 v = ((const float4*)emb)[z[n] * 32 + q];
    ((float4*)h)[idx] = v;
    uint2 p;
    __half2 h0 = __floats2half2_rn(v.x, v.y);
    __half2 h1 = __floats2half2_rn(v.z, v.w);
    p.x = *(unsigned int*)&h0;
    p.y = *(unsigned int*)&h1;
    ((uint2*)g_hh)[idx] = p;
}

__global__ void k_zero(int n) {
    int i = blockIdx.x * blockDim.x + threadIdx.x;
    if (i < n) g_deg[i] = 0;
}

// ---------------- initial lin1 (padded smem) ----------------
__global__ void __launch_bounds__(256) k_lin1(int N) {
    __shared__ __align__(16) char smem_raw[64 * AP * 2 + 128 * AP * 2];
    __half* As = (__half*)smem_raw;
    __half* Bs = (__half*)(smem_raw + 64 * AP * 2);
    float*  Os = (float*)smem_raw;

    const int tid = threadIdx.x;
    const int wid = tid >> 5;
    const int m0 = blockIdx.x * 64;
    const __half* Bw = g_w1t;  // layer 0

#pragma unroll
    for (int i = 0; i < 4; i++) {
        int lin = i * 256 + tid;
        int r = lin >> 4, c = lin & 15;
        int gr = m0 + r;
        uint4 v = make_uint4(0, 0, 0, 0);
        if (gr < N) v = *(const uint4*)(g_hh + (size_t)gr * HH + c * 8);
        *(uint4*)(As + r * AP + c * 8) = v;
    }
#pragma unroll
    for (int i = 0; i < 8; i++) {
        int lin = i * 256 + tid;
        int r = lin >> 4, c = lin & 15;
        *(uint4*)(Bs + r * AP + c * 8) = *(const uint4*)(Bw + lin * 8);
    }
    __syncthreads();

    const int wm = wid & 3;
    const int wn = wid >> 2;
    wmma::fragment<wmma::accumulator, 16, 16, 16, float> accf[4];
#pragma unroll
    for (int n = 0; n < 4; n++) wmma::fill_fragment(accf[n], 0.f);
#pragma unroll
    for (int ks = 0; ks < 8; ks++) {
        wmma::fragment<wmma::matrix_a, 16, 16, 16, __half, wmma::row_major> af;
        wmma::load_matrix_sync(af, As + (wm * 16) * AP + ks * 16, AP);
#pragma unroll
        for (int n = 0; n < 4; n++) {
            wmma::fragment<wmma::matrix_b, 16, 16, 16, __half, wmma::col_major> bf;
            wmma::load_matrix_sync(bf, Bs + (wn * 64 + n * 16) * AP + ks * 16, AP);
            wmma::mma_sync(accf[n], af, bf, accf[n]);
        }
    }
    __syncthreads();
#pragma unroll
    for (int n = 0; n < 4; n++)
        wmma::store_matrix_sync(Os + (wm * 16) * OP + wn * 64 + n * 16,
                                accf[n], OP, wmma::mem_row_major);
    __syncthreads();

#pragma unroll
    for (int i = 0; i < 8; i++) {
        int lin = i * 256 + tid;
        int r = lin >> 5, c4 = lin & 31;
        int gr = m0 + r;
        if (gr >= N) continue;
        float4 v = *(float4*)(Os + r * OP + c4 * 4);
        uint2 p;
        __half2 h0 = __floats2half2_rn(v.x, v.y);
        __half2 h1 = __floats2half2_rn(v.z, v.w);
        p.x = *(unsigned int*)&h0;
        p.y = *(unsigned int*)&h1;
        *(uint2*)(g_xh + (size_t)gr * HH + c4 * 4) = p;
    }
}

// ---------------- Wf(d) table build ----------------
__global__ void __launch_bounds__(128) k_table(
    const float* __restrict__ w1, const float* __restrict__ b1,
    const float* __restrict__ w2, const float* __restrict__ b2)
{
    __shared__ float ea[PTS][GG];
    __shared__ float t1[PTS][HH];
    const int l  = blockIdx.y;
    const int k0 = blockIdx.x * PTS;
    const int f  = threadIdx.x;

    for (int idx = f; idx < PTS * GG; idx += 128) {
        int p = idx / GG, g = idx % GG;
        float d  = (float)(k0 + p) * DSTEP;
        float dd = d - (float)g * GSTEP;
        ea[p][g] = expf(GCOEFF * dd * dd);
    }
    __syncthreads();

    float acc[PTS];
#pragma unroll
    for (int p = 0; p < PTS; p++) acc[p] = 0.f;
    const float* W1 = w1 + l * GG * HH;
    for (int g = 0; g < GG; g++) {
        float w = W1[g * HH + f];
#pragma unroll
        for (int p = 0; p < PTS; p++) acc[p] += ea[p][g] * w;
    }
    float bb = b1[l * HH + f];
#pragma unroll
    for (int p = 0; p < PTS; p++) t1[p][f] = sspf(acc[p] + bb);
    __syncthreads();

#pragma unroll
    for (int p = 0; p < PTS; p++) acc[p] = 0.f;
    const float* W2 = w2 + l * HH * HH;
    for (int ff = 0; ff < HH; ff++) {
        float w = W2[ff * HH + f];
#pragma unroll
        for (int p = 0; p < PTS; p++) acc[p] += t1[p][ff] * w;
    }
    float b2v = b2[l * HH + f];
#pragma unroll
    for (int p = 0; p < PTS; p++) {
        float d = (float)(k0 + p) * DSTEP;
        float C = 0.5f * (cosf(d * (PIF / 10.f)) + 1.f);
        g_tab[(size_t)(l * KTAB + k0 + p) * HH + f] =
            __float2half((acc[p] + b2v) * C);
    }
}

// ---------------- CSR build ----------------
__global__ void k_prep(const int* __restrict__ ei, const float* __restrict__ pos, int E) {
    int stride = gridDim.x * blockDim.x;
    for (int e = blockIdx.x * blockDim.x + threadIdx.x; e < E; e += stride) {
        int r = ei[e], c = ei[E + e];
        float dx = pos[r * 3 + 0] - pos[c * 3 + 0];
        float dy = pos[r * 3 + 1] - pos[c * 3 + 1];
        float dz = pos[r * 3 + 2] - pos[c * 3 + 2];
        float d = sqrtf(dx * dx + dy * dy + dz * dz);
        float u = d * TABSCALE;
        int k = (int)u;
        if (k > KTAB - 2) k = KTAB - 2;
        if (k < 0) k = 0;
        float t = u - (float)k;
        g_me[e] = make_int2(r | (k << 14), __float_as_int(t));
        atomicAdd(&g_deg[c], 1);
    }
}

__global__ void __launch_bounds__(1024) k_scan(int n) {
    __shared__ int sw[32];
    const int PER = 10;
    int t = threadIdx.x, lane = t & 31, w = t >> 5;
    int base = t * PER;
    int local[PER];
    int sum = 0;
#pragma unroll
    for (int i = 0; i < PER; i++) {
        int v = (base + i < n) ? g_deg[base + i] : 0;
        local[i] = sum;
        sum += v;
    }
    int inc = sum;
#pragma unroll
    for (int off = 1; off < 32; off <<= 1) {
        int v = __shfl_up_sync(0xffffffffu, inc, off);
        if (lane >= off) inc += v;
    }
    if (lane == 31) sw[w] = inc;
    __syncthreads();
    if (w == 0) {
        int v = sw[lane];
        int s2 = v;
#pragma unroll
        for (int off = 1; off < 32; off <<= 1) {
            int u2 = __shfl_up_sync(0xffffffffu, s2, off);
            if (lane >= off) s2 += u2;
        }
        sw[lane] = s2 - v;
        if (lane == 31) g_start[n] = s2;
    }
    __syncthreads();
    int excl = sw[w] + inc - sum;
#pragma unroll
    for (int i = 0; i < PER; i++) {
        if (base + i < n) {
            int st = excl + local[i];
            g_start[base + i]  = st;
            g_cursor[base + i] = st;
        }
    }
}

__global__ void k_scatter(const int* __restrict__ ei, int E) {
    int stride = gridDim.x * blockDim.x;
    for (int e = blockIdx.x * blockDim.x + threadIdx.x; e < E; e += stride) {
        int c = ei[E + e];
        int p = atomicAdd(&g_cursor[c], 1);
        g_se[p] = g_me[e];
    }
}

// ---------------- message aggregation ----------------
// fp16 lerp, MLP x2. Streaming loads (__ldcs) for x rows and edge meta keep
// L1 reserved for the 512KB/layer table (default-cached loads).
__global__ void __launch_bounds__(256) k_agg(int l, int N) {
    int warp = (blockIdx.x * 256 + threadIdx.x) >> 5;
    int lane = threadIdx.x & 31;
    if (warp >= N) return;
    const __half* __restrict__ tab = g_tab + (size_t)l * KTAB * HH;
    int beg = g_start[warp], end = g_start[warp + 1];
    const int flane = lane & 15;
    const int esub  = lane >> 4;
    float acc[8];
#pragma unroll
    for (int q = 0; q < 8; q++) acc[q] = 0.f;

    for (int e0 = beg; e0 < end; e0 += 32) {
        int idx = e0 + lane;
        int2 mv = make_int2(0, 0);
        if (idx < end) mv = __ldcs(&g_se[idx]);
        int cnt = min(32, end - e0);
        for (int s = 0; s < cnt; s += 4) {
            int j1 = s + esub;
            int j2 = s + 2 + esub;
            int mj1 = __shfl_sync(0xffffffffu, mv.x, j1 & 31);
            int ti1 = __shfl_sync(0xffffffffu, mv.y, j1 & 31);
            int mj2 = __shfl_sync(0xffffffffu, mv.x, j2 & 31);
            int ti2 = __shfl_sync(0xffffffffu, mv.y, j2 & 31);
            bool p1 = j1 < cnt, p2 = j2 < cnt;
            uint4 xr1, w01, w11, xr2, w02, w12;
            int k1 = mj1 >> 14, k2 = mj2 >> 14;
            int s1 = mj1 & 0x3FFF, s2v = mj2 & 0x3FFF;
            if (p1) {
                xr1 = __ldcs((const uint4*)(g_xh + (size_t)s1 * HH + flane * 8));
                w01 = *(const uint4*)(tab + (size_t)k1 * HH + flane * 8);
                w11 = *(const uint4*)(tab + (size_t)(k1 + 1) * HH + flane * 8);
            }
            if (p2) {
                xr2 = __ldcs((const uint4*)(g_xh + (size_t)s2v * HH + flane * 8));
                w02 = *(const uint4*)(tab + (size_t)k2 * HH + flane * 8);
                w12 = *(const uint4*)(tab + (size_t)(k2 + 1) * HH + flane * 8);
            }
            if (p1) {
                __half2 t2 = __float2half2_rn(__int_as_float(ti1));
                const __half2* xv = (const __half2*)&xr1;
                const __half2* a0 = (const __half2*)&w01;
                const __half2* a1 = (const __half2*)&w11;
#pragma unroll
                for (int q = 0; q < 4; q++) {
                    __half2 dd = __hsub2(a1[q], a0[q]);
                    __half2 w  = __hfma2(t2, dd, a0[q]);
                    __half2 p  = __hmul2(w, xv[q]);
                    float2 pf = __half22float2(p);
                    acc[q * 2 + 0] += pf.x;
                    acc[q * 2 + 1] += pf.y;
                }
            }
            if (p2) {
                __half2 t2 = __float2half2_rn(__int_as_float(ti2));
                const __half2* xv = (const __half2*)&xr2;
                const __half2* a0 = (const __half2*)&w02;
                const __half2* a1 = (const __half2*)&w12;
#pragma unroll
                for (int q = 0; q < 4; q++) {
                    __half2 dd = __hsub2(a1[q], a0[q]);
                    __half2 w  = __hfma2(t2, dd, a0[q]);
                    __half2 p  = __hmul2(w, xv[q]);
                    float2 pf = __half22float2(p);
                    acc[q * 2 + 0] += pf.x;
                    acc[q * 2 + 1] += pf.y;
                }
            }
        }
    }
#pragma unroll
    for (int q = 0; q < 8; q++)
        acc[q] += __shfl_xor_sync(0xffffffffu, acc[q], 16);

    if (esub == 0) {
        uint4 outv;
        __half2* op = (__half2*)&outv;
#pragma unroll
        for (int q = 0; q < 4; q++)
            op[q] = __floats2half2_rn(acc[q * 2], acc[q * 2 + 1]);
        *(uint4*)(g_aggh + (size_t)warp * HH + flane * 8) = outv;
    }
}

// ---------------- fused GEMM chain (padded smem) ----------------
template <bool NEXT>
__global__ void __launch_bounds__(256, 2) k_chain(
    int l, const float* __restrict__ b2p, const float* __restrict__ b3p,
    float* __restrict__ h, int N)
{
    extern __shared__ __align__(16) char sm[];
    __half* As = (__half*)sm;                               // 64 x AP
    __half* Bs = (__half*)(sm + 64 * AP * 2);               // 128 x AP
    float*  Os = (float*)(sm + 64 * AP * 2 + 128 * AP * 2); // 64 x OP

    const int tid = threadIdx.x;
    const int wid = tid >> 5;
    const int m0  = blockIdx.x * 64;

#pragma unroll
    for (int i = 0; i < 4; i++) {
        int lin = i * 256 + tid;
        int r = lin >> 4, c = lin & 15;
        int gr = m0 + r;
        uint4 v = make_uint4(0, 0, 0, 0);
        if (gr < N) v = *(const uint4*)(g_aggh + (size_t)gr * HH + c * 8);
        *(uint4*)(As + r * AP + c * 8) = v;
    }

    auto run_gemm = [&](const __half* __restrict__ Bw) {
        __syncthreads();
#pragma unroll
        for (int i = 0; i < 8; i++) {
            int lin = i * 256 + tid;
            int r = lin >> 4, c = lin & 15;
            *(uint4*)(Bs + r * AP + c * 8) = *(const uint4*)(Bw + lin * 8);
        }
        __syncthreads();
        for (int t2 = wid; t2 < 16; t2 += 8) {
            int wm = t2 & 3, wn = t2 >> 2;
            wmma::fragment<wmma::accumulator, 16, 16, 16, float> c0, c1;
            wmma::fill_fragment(c0, 0.f);
            wmma::fill_fragment(c1, 0.f);
#pragma unroll
            for (int ks = 0; ks < 8; ks++) {
                wmma::fragment<wmma::matrix_a, 16, 16, 16, __half, wmma::row_major> af;
                wmma::load_matrix_sync(af, As + (wm * 16) * AP + ks * 16, AP);
                wmma::fragment<wmma::matrix_b, 16, 16, 16, __half, wmma::col_major> bf0, bf1;
                wmma::load_matrix_sync(bf0, Bs + (wn * 32) * AP + ks * 16, AP);
                wmma::load_matrix_sync(bf1, Bs + (wn * 32 + 16) * AP + ks * 16, AP);
                wmma::mma_sync(c0, af, bf0, c0);
                wmma::mma_sync(c1, af, bf1, c1);
            }
            wmma::store_matrix_sync(Os + (wm * 16) * OP + wn * 32, c0, OP,
                                    wmma::mem_row_major);
            wmma::store_matrix_sync(Os + (wm * 16) * OP + wn * 32 + 16, c1, OP,
                                    wmma::mem_row_major);
        }
        __syncthreads();
    };

    // Stage 1: u = ssp(agg @ W2 + b2) -> As
    run_gemm(g_w2t + (size_t)l * HH * HH);
#pragma unroll
    for (int i = 0; i < 8; i++) {
        int lin = i * 256 + tid;
        int r = lin >> 5, c4 = lin & 31;
        float4 v = *(float4*)(Os + r * OP + c4 * 4);
        const float4 bi = *(const float4*)(b2p + c4 * 4);
        v.x = sspf(v.x + bi.x); v.y = sspf(v.y + bi.y);
        v.z = sspf(v.z + bi.z); v.w = sspf(v.w + bi.w);
        uint2 p;
        __half2 h0 = __floats2half2_rn(v.x, v.y);
        __half2 h1 = __floats2half2_rn(v.z, v.w);
        p.x = *(unsigned int*)&h0;
        p.y = *(unsigned int*)&h1;
        *(uint2*)(As + (size_t)r * AP + c4 * 4) = p;
    }

    // Stage 2: v = u @ W3 + b3 + h ; h = v -> As
    run_gemm(g_w3t + (size_t)l * HH * HH);
#pragma unroll
    for (int i = 0; i < 8; i++) {
        int lin = i * 256 + tid;
        int r = lin >> 5, c4 = lin & 31;
        int gr = m0 + r;
        float4 v = *(float4*)(Os + r * OP + c4 * 4);
        const float4 bi = *(const float4*)(b3p + c4 * 4);
        v.x += bi.x; v.y += bi.y; v.z += bi.z; v.w += bi.w;
        if (gr < N) {
            float4 o = *(float4*)(h + (size_t)gr * HH + c4 * 4);
            v.x += o.x; v.y += o.y; v.z += o.z; v.w += o.w;
            *(float4*)(h + (size_t)gr * HH + c4 * 4) = v;
        }
        uint2 p;
        __half2 h0 = __floats2half2_rn(v.x, v.y);
        __half2 h1 = __floats2half2_rn(v.z, v.w);
        p.x = *(unsigned int*)&h0;
        p.y = *(unsigned int*)&h1;
        *(uint2*)(As + (size_t)r * AP + c4 * 4) = p;
    }

    // Stage 3: x_{l+1} = v @ W1[l+1] -> g_xh
    if (NEXT) {
        run_gemm(g_w1t + (size_t)(l + 1) * HH * HH);
#pragma unroll
        for (int i = 0; i < 8; i++) {
            int lin = i * 256 + tid;
            int r = lin >> 5, c4 = lin & 31;
            int gr = m0 + r;
            if (gr >= N) continue;
            float4 v = *(float4*)(Os + r * OP + c4 * 4);
            uint2 p;
            __half2 h0 = __floats2half2_rn(v.x, v.y);
            __half2 h1 = __floats2half2_rn(v.z, v.w);
            p.x = *(unsigned int*)&h0;
            p.y = *(unsigned int*)&h1;
            *(uint2*)(g_xh + (size_t)gr * HH + c4 * 4) = p;
        }
    }
}

// ---------------- launch ----------------
extern "C" void kernel_launch(void* const* d_in, const int* in_sizes, int n_in,
                              void* d_out, int out_size)
{
    const int*   z      = (const int*)d_in[0];
    const float* pos    = (const float*)d_in[1];
    const int*   ei     = (const int*)d_in[2];
    const float* emb    = (const float*)d_in[3];
    const float* mlp_w1 = (const float*)d_in[4];
    const float* mlp_b1 = (const float*)d_in[5];
    const float* mlp_w2 = (const float*)d_in[6];
    const float* mlp_b2 = (const float*)d_in[7];
    const float* lin1_w = (const float*)d_in[8];
    const float* lin2_w = (const float*)d_in[9];
    const float* lin2_b = (const float*)d_in[10];
    const float* lin_w  = (const float*)d_in[11];
    const float* lin_b  = (const float*)d_in[12];

    const int N = in_sizes[0];
    const int E = in_sizes[2] / 2;
    float* h = (float*)d_out;

    const int SMEM_CHAIN = 64 * AP * 2 + 128 * AP * 2 + 64 * OP * 4;
    static bool s_init = false;
    static cudaStream_t s_csr, s_tab;
    static cudaEvent_t s_evRoot, s_evCsr, s_evTab;
    if (!s_init) {
        cudaFuncSetAttribute(k_chain<true>,
                             cudaFuncAttributeMaxDynamicSharedMemorySize, SMEM_CHAIN);
        cudaFuncSetAttribute(k_chain<false>,
                             cudaFuncAttributeMaxDynamicSharedMemorySize, SMEM_CHAIN);
        cudaStreamCreateWithFlags(&s_csr, cudaStreamNonBlocking);
        cudaStreamCreateWithFlags(&s_tab, cudaStreamNonBlocking);
        cudaEventCreateWithFlags(&s_evRoot, cudaEventDisableTiming);
        cudaEventCreateWithFlags(&s_evCsr, cudaEventDisableTiming);
        cudaEventCreateWithFlags(&s_evTab, cudaEventDisableTiming);
        s_init = true;
    }

    const int gb = (N + 63) / 64;
    const int ga = (N + 7) / 8;

    cudaEventRecord(s_evRoot, 0);
    cudaStreamWaitEvent(s_csr, s_evRoot, 0);
    cudaStreamWaitEvent(s_tab, s_evRoot, 0);

    // CSR stream
    k_zero<<<(N + 255) / 256, 256, 0, s_csr>>>(N);
    k_prep<<<313, 256, 0, s_csr>>>(ei, pos, E);
    k_scan<<<1, 1024, 0, s_csr>>>(N);
    k_scatter<<<313, 256, 0, s_csr>>>(ei, E);
    cudaEventRecord(s_evCsr, s_csr);

    // table stream
    dim3 tg(KTAB / PTS, LL);
    k_table<<<tg, 128, 0, s_tab>>>(mlp_w1, mlp_b1, mlp_w2, mlp_b2);
    cudaEventRecord(s_evTab, s_tab);

    // main stream
    k_wconv<<<(3 * LL * HH * HH + 255) / 256, 256>>>(lin1_w, lin2_w, lin_w);
    k_embed<<<(N * 32 + 255) / 256, 256>>>(z, emb, h, N);
    k_lin1<<<gb, 256>>>(N);

    cudaStreamWaitEvent(0, s_evCsr, 0);
    cudaStreamWaitEvent(0, s_evTab, 0);

    for (int l = 0; l < LL; l++) {
        k_agg<<<ga, 256>>>(l, N);
        if (l < LL - 1)
            k_chain<true><<<gb, 256, SMEM_CHAIN>>>(
                l, lin2_b + (size_t)l * HH, lin_b + (size_t)l * HH, h, N);
        else
            k_chain<false><<<gb, 256, SMEM_CHAIN>>>(
                l, lin2_b + (size_t)l * HH, lin_b + (size_t)l * HH, h, N);
    }
}